// round 12
// baseline (speedup 1.0000x reference)
#include <cuda_runtime.h>
#include <math.h>

// out[b,c,:] = irfft( rfft(x,16384) * Kspec[c], 16384 )[:8192]
// R11 base (radix-8 Stockham, fused seams, per-pass skew) with twiddle tables
// hoisted to a tiny init kernel: CTAs copy tables gmem->smem instead of
// recomputing 9 sincospif per thread. Stage stride s is a template parameter.

#define N_FFT   8192
#define HALF_N  4096
#define NT      1024
#define L_SEQ   8192
#define NCHAN   256
#define NROWS   2048

#define BUF_PAD 9216
#define SKM(a,M) ((a) + (M) * ((a) >> 4))
#define TWT     1024
#define TWH_N   2052

__device__ float2 g_kspec[(size_t)NCHAN * (N_FFT + 1)];
__device__ float2 g_tws[7 * TWT];     // g_tws[(m-1)*1024+e] = e^{-2 pi i m e/8192}
__device__ float2 g_twh[TWH_N];       // g_twh[k] = e^{-i pi k/8192}, k <= 2048

__device__ __forceinline__ float2 cmul(float2 a, float2 b) {
    return make_float2(a.x * b.x - a.y * b.y, a.x * b.y + a.y * b.x);
}
__device__ __forceinline__ float2 cmulc(float2 a, float2 b) {   // a * conj(b)
    return make_float2(a.x * b.x + a.y * b.y, a.y * b.x - a.x * b.y);
}
__device__ __forceinline__ float2 cadd(float2 a, float2 b) { return make_float2(a.x + b.x, a.y + b.y); }
__device__ __forceinline__ float2 csub(float2 a, float2 b) { return make_float2(a.x - b.x, a.y - b.y); }

template <int INV>
__device__ __forceinline__ void dft8(float2* v) {
    const float u = 0.70710678118654752f;
    float2 apc = cadd(v[0], v[4]), amc = csub(v[0], v[4]);
    float2 bpd = cadd(v[2], v[6]), bmd = csub(v[2], v[6]);
    float2 E0 = cadd(apc, bpd), E2 = csub(apc, bpd), E1, E3;
    if (!INV) { E1 = make_float2(amc.x + bmd.y, amc.y - bmd.x); E3 = make_float2(amc.x - bmd.y, amc.y + bmd.x); }
    else      { E1 = make_float2(amc.x - bmd.y, amc.y + bmd.x); E3 = make_float2(amc.x + bmd.y, amc.y - bmd.x); }
    apc = cadd(v[1], v[5]); amc = csub(v[1], v[5]);
    bpd = cadd(v[3], v[7]); bmd = csub(v[3], v[7]);
    float2 O0 = cadd(apc, bpd), O2 = csub(apc, bpd), O1, O3;
    if (!INV) { O1 = make_float2(amc.x + bmd.y, amc.y - bmd.x); O3 = make_float2(amc.x - bmd.y, amc.y + bmd.x); }
    else      { O1 = make_float2(amc.x - bmd.y, amc.y + bmd.x); O3 = make_float2(amc.x + bmd.y, amc.y - bmd.x); }
    float2 T1, T2, T3;
    if (!INV) {
        T1 = make_float2(u * (O1.x + O1.y), u * (O1.y - O1.x));
        T2 = make_float2(O2.y, -O2.x);
        T3 = make_float2(u * (O3.y - O3.x), -u * (O3.x + O3.y));
    } else {
        T1 = make_float2(u * (O1.x - O1.y), u * (O1.x + O1.y));
        T2 = make_float2(-O2.y, O2.x);
        T3 = make_float2(-u * (O3.x + O3.y), u * (O3.x - O3.y));
    }
    v[0] = cadd(E0, O0); v[4] = csub(E0, O0);
    v[1] = cadd(E1, T1); v[5] = csub(E1, T1);
    v[2] = cadd(E2, T2); v[6] = csub(E2, T2);
    v[3] = cadd(E3, T3); v[7] = csub(E3, T3);
}

// forward dft8 with v[4..7] == 0 implied
__device__ __forceinline__ void dft8_half(float2* v) {
    const float u = 0.70710678118654752f;
    float2 E0 = cadd(v[0], v[2]), E2 = csub(v[0], v[2]);
    float2 E1 = make_float2(v[0].x + v[2].y, v[0].y - v[2].x);
    float2 E3 = make_float2(v[0].x - v[2].y, v[0].y + v[2].x);
    float2 O0 = cadd(v[1], v[3]), O2 = csub(v[1], v[3]);
    float2 O1 = make_float2(v[1].x + v[3].y, v[1].y - v[3].x);
    float2 O3 = make_float2(v[1].x - v[3].y, v[1].y + v[3].x);
    float2 T1 = make_float2(u * (O1.x + O1.y), u * (O1.y - O1.x));
    float2 T2 = make_float2(O2.y, -O2.x);
    float2 T3 = make_float2(u * (O3.y - O3.x), -u * (O3.x + O3.y));
    v[0] = cadd(E0, O0); v[4] = csub(E0, O0);
    v[1] = cadd(E1, T1); v[5] = csub(E1, T1);
    v[2] = cadd(E2, T2); v[6] = csub(E2, T2);
    v[3] = cadd(E3, T3); v[7] = csub(E3, T3);
}

// radix-8 Stockham stage; S = stride (compile-time), RM/WM = read/write skews
template <int INV, int RM, int WM, int S>
__device__ __forceinline__ void stage_r8(const float2* __restrict__ x, float2* __restrict__ y,
                                         const float2* __restrict__ tws, int tid) {
    const int q = tid & (S - 1);
    const int e = tid - q;
    float2 v[8];
#pragma unroll
    for (int j = 0; j < 8; j++) v[j] = x[SKM(tid + (j << 10), RM)];
    dft8<INV>(v);
    const int o = q + (e << 3);
    y[SKM(o, WM)] = v[0];
#pragma unroll
    for (int m = 1; m < 8; m++) {
        float2 w = tws[((m - 1) << 10) + e];
        y[SKM(o + m * S, WM)] = INV ? cmulc(v[m], w) : cmul(w, v[m]);
    }
}

// stage-1 (s=1) write from registers, e = tid  (skew mult 1: conflict-free)
__device__ __forceinline__ void stage1_write(float2* __restrict__ y, const float2* v,
                                             const float2* __restrict__ tws, int tid) {
    const int o = tid << 3;
    y[SKM(o, 1)] = v[0];
#pragma unroll
    for (int m = 1; m < 8; m++) {
        float2 w = tws[((m - 1) << 10) + tid];
        y[SKM(o + m, 1)] = cmul(w, v[m]);
    }
}

// copy precomputed tables from global (L2-resident) into smem
__device__ __forceinline__ void load_tw(float2* tws, float2* twh, int tid) {
#pragma unroll
    for (int i = 0; i < 7; i++) tws[tid + (i << 10)] = g_tws[tid + (i << 10)];
#pragma unroll
    for (int i = tid; i < TWH_N; i += NT) twh[i] = g_twh[i];
}

// unpack pair: Z[k], Z[8192-k], E=e^{-i pi k/8192} -> X[k], X[8192-k]
__device__ __forceinline__ void unpack_pair(float2 Zk, float2 Zn, float2 E,
                                            float2* Xk, float2* Xn) {
    float2 A = make_float2(0.5f * (Zk.x + Zn.x), 0.5f * (Zk.y - Zn.y));
    float2 D = make_float2(0.5f * (Zk.x - Zn.x), 0.5f * (Zk.y + Zn.y));
    float2 B = make_float2(D.y, -D.x);
    float2 EB = cmul(E, B);
    *Xk = make_float2(A.x + EB.x, A.y + EB.y);
    *Xn = make_float2(A.x - EB.x, -(A.y - EB.y));
}

__device__ __forceinline__ void spec_pair(float2 Zk, float2 Zn, float2 Kk, float2 Kn,
                                          float2 E, float2* Wk, float2* Wn) {
    float2 Xk, Xn;
    unpack_pair(Zk, Zn, E, &Xk, &Xn);
    float2 Yk = cmul(Xk, Kk);
    float2 Yn = cmul(Xn, Kn);
    float2 Ay = make_float2(0.5f * (Yk.x + Yn.x), 0.5f * (Yk.y - Yn.y));
    float2 Dy = make_float2(0.5f * (Yk.x - Yn.x), 0.5f * (Yk.y + Yn.y));
    float2 By = cmulc(Dy, E);
    *Wk = make_float2(Ay.x - By.y,  Ay.y + By.x);
    *Wn = make_float2(Ay.x + By.y, -Ay.y + By.x);
}

__device__ __forceinline__ float smooth_squash(const float* rk, int i) {
    float ssum = 0.f;
#pragma unroll
    for (int d = -3; d <= 3; d++) {
        int j = i + d;
        j = (j < 0) ? -j : j;
        j = (j > L_SEQ - 1) ? (2 * (L_SEQ - 1) - j) : j;
        ssum += rk[j];
    }
    float v = ssum * (1.0f / 7.0f);
    float a = fabsf(v) - 0.003f;
    return (a > 0.f) ? copysignf(a, v) : 0.f;
}

// smem: b0[BUF_PAD] | b1[BUF_PAD] | tws[7*1024] | twh[2052]
#define SMEM_BYTES ((2 * BUF_PAD + 7 * TWT + TWH_N) * (int)sizeof(float2))

// ---------------------------------------------------------------------------
__global__ void init_tw_kernel() {
    const int j = blockIdx.x * blockDim.x + threadIdx.x;
    float s, c;
    if (j < 7 * TWT) {
        const int m = (j >> 10) + 1;
        const int e = j & (TWT - 1);
        sincospif((float)(m * e) * (1.0f / 4096.0f), &s, &c);
        g_tws[j] = make_float2(c, -s);
    }
    if (j < TWH_N) {
        sincospif((float)j * (1.0f / 8192.0f), &s, &c);
        g_twh[j] = make_float2(c, -s);
    }
}

// ---------------------------------------------------------------------------
__global__ void __launch_bounds__(NT, 1) kspec_kernel(const float* __restrict__ kern) {
    extern __shared__ float2 sm2[];
    float2* b0  = sm2;
    float2* b1  = sm2 + BUF_PAD;
    float2* tws = sm2 + 2 * BUF_PAD;
    float2* twh = tws + 7 * TWT;
    float*  rk  = (float*)b0;          // overlay b0: consumed before stage-1 write

    const int c   = blockIdx.x;
    const int tid = threadIdx.x;
    const float* kr = kern + (size_t)c * L_SEQ;

    for (int i = tid; i < L_SEQ; i += NT) rk[i] = kr[i];
    load_tw(tws, twh, tid);
    __syncthreads();

    {   // fused stage 1 from smooth/squash registers -> b1 (skew 1)
        float2 v[8];
#pragma unroll
        for (int j = 0; j < 4; j++) {
            const int n = tid + (j << 10);
            v[j] = make_float2(smooth_squash(rk, 2 * n), smooth_squash(rk, 2 * n + 1));
        }
        __syncthreads();               // all rk reads done before b1 write? b1 != rk; rk=b0 -> safe
        dft8_half(v);
        stage1_write(b1, v, tws, tid);
    }
    __syncthreads();
    stage_r8<0,1,2,8>(b1, b0, tws, tid);   __syncthreads();
    stage_r8<0,2,1,64>(b0, b1, tws, tid);  __syncthreads();
    stage_r8<0,1,1,512>(b1, b0, tws, tid); __syncthreads();
    // P = b0 (skew 1); fused r2 finisher + unpack + store (scaled 1/N)
    float2* Kc = g_kspec + (size_t)c * (N_FFT + 1);
    const float inv = 1.0f / (float)N_FFT;
#pragma unroll 1
    for (int u = 0; u < 2; u++) {
        const int q = tid + (u << 10);
        if (q == 0) {
            float2 Pa = b0[SKM(0,1)],    Pb = b0[SKM(4096,1)];
            float2 Pc = b0[SKM(2048,1)], Pd = b0[SKM(6144,1)];
            float2 Z0 = cadd(Pa, Pb), Z4 = csub(Pa, Pb);
            float2 Z2 = cadd(Pc, Pd), Z6 = csub(Pc, Pd);
            Kc[0]     = make_float2((Z0.x + Z0.y) * inv, 0.f);
            Kc[N_FFT] = make_float2((Z0.x - Z0.y) * inv, 0.f);
            Kc[4096]  = make_float2(Z4.x * inv, -Z4.y * inv);
            float2 X2, X6;
            unpack_pair(Z2, Z6, twh[2048], &X2, &X6);
            Kc[2048] = make_float2(X2.x * inv, X2.y * inv);
            Kc[6144] = make_float2(X6.x * inv, X6.y * inv);
        } else {
            const int r = 4096 - q;
            float2 Pa = b0[SKM(q,1)], Pb = b0[SKM(q + 4096,1)];
            float2 Pc = b0[SKM(r,1)], Pd = b0[SKM(r + 4096,1)];
            float2 Zq = cadd(Pa, Pb), Zq4 = csub(Pa, Pb);
            float2 Zr = cadd(Pc, Pd), Znq = csub(Pc, Pd);
            float2 Eq = twh[q];
            float2 Er = make_float2(-Eq.y, -Eq.x);        // E(4096-q)
            float2 Xq, Xnq, Xr, Xpq;
            unpack_pair(Zq, Znq, Eq, &Xq, &Xnq);
            unpack_pair(Zr, Zq4, Er, &Xr, &Xpq);
            Kc[q]         = make_float2(Xq.x * inv,  Xq.y * inv);
            Kc[N_FFT - q] = make_float2(Xnq.x * inv, Xnq.y * inv);
            Kc[r]         = make_float2(Xr.x * inv,  Xr.y * inv);
            Kc[4096 + q]  = make_float2(Xpq.x * inv, Xpq.y * inv);
        }
    }
}

// ---------------------------------------------------------------------------
__global__ void __launch_bounds__(NT, 1) conv_kernel(const float* __restrict__ x,
                                                     float* __restrict__ out) {
    extern __shared__ float2 sm2[];
    float2* b0  = sm2;
    float2* b1  = sm2 + BUF_PAD;
    float2* tws = sm2 + 2 * BUF_PAD;
    float2* twh = tws + 7 * TWT;

    const int row = blockIdx.x;
    const int c   = row & (NCHAN - 1);
    const int tid = threadIdx.x;
    const float2* xr = (const float2*)(x + (size_t)row * L_SEQ);

    load_tw(tws, twh, tid);

    {   // fwd stage 1: global read fused (upper half zero) -> b0 (skew 1)
        float2 v[8];
#pragma unroll
        for (int j = 0; j < 4; j++) v[j] = xr[tid + (j << 10)];
        __syncthreads();               // tables ready before stage1 twiddle reads
        dft8_half(v);
        stage1_write(b0, v, tws, tid);
    }
    __syncthreads();
    stage_r8<0,1,2,8>(b0, b1, tws, tid);   __syncthreads();
    stage_r8<0,2,1,64>(b1, b0, tws, tid);  __syncthreads();
    stage_r8<0,1,1,512>(b0, b1, tws, tid); __syncthreads();
    // P = b1 (skew 1)

    // fused: fwd r2 finisher + spectral multiply + inv r2 opener -> b0 (skew 1)
    const float2* Kc = g_kspec + (size_t)c * (N_FFT + 1);
#pragma unroll 1
    for (int u = 0; u < 2; u++) {
        const int q = tid + (u << 10);
        if (q == 0) {
            float2 Pa = b1[SKM(0,1)],    Pb = b1[SKM(4096,1)];
            float2 Pc = b1[SKM(2048,1)], Pd = b1[SKM(6144,1)];
            float2 Z0 = cadd(Pa, Pb), Z4 = csub(Pa, Pb);
            float2 Z2 = cadd(Pc, Pd), Z6 = csub(Pc, Pd);
            float X0 = Z0.x + Z0.y, XN = Z0.x - Z0.y;
            float2 K0 = Kc[0], KN = Kc[N_FFT];
            float2 Y0 = make_float2(X0 * K0.x, X0 * K0.y);
            float2 YN = make_float2(XN * KN.x, XN * KN.y);
            float2 Ay = make_float2(0.5f * (Y0.x + YN.x), 0.5f * (Y0.y - YN.y));
            float2 Dy = make_float2(0.5f * (Y0.x - YN.x), 0.5f * (Y0.y + YN.y));
            float2 W0 = make_float2(Ay.x - Dy.y, Ay.y + Dy.x);
            float2 W4, Wd;
            spec_pair(Z4, Z4, Kc[4096], Kc[4096], make_float2(0.f, -1.f), &W4, &Wd);
            float2 W2, W6;
            spec_pair(Z2, Z6, Kc[2048], Kc[6144], twh[2048], &W2, &W6);
            b0[SKM(0,1)] = cadd(W0, W4);
            b0[SKM(1,1)] = csub(W0, W4);
            b0[SKM(4096,1)] = cadd(W2, W6);
            float2 t = csub(W2, W6);                 // * winv(2048) = i
            b0[SKM(4097,1)] = make_float2(-t.y, t.x);
        } else {
            const int r = 4096 - q;
            float2 Pa = b1[SKM(q,1)], Pb = b1[SKM(q + 4096,1)];
            float2 Pc = b1[SKM(r,1)], Pd = b1[SKM(r + 4096,1)];
            float2 Zq = cadd(Pa, Pb), Zq4 = csub(Pa, Pb);
            float2 Zr = cadd(Pc, Pd), Znq = csub(Pc, Pd);
            float2 Eq = twh[q];
            float2 Er = make_float2(-Eq.y, -Eq.x);
            float2 Wq, Wnq, Wr, Wpq;
            spec_pair(Zq, Znq, Kc[q], Kc[N_FFT - q], Eq, &Wq, &Wnq);
            spec_pair(Zr, Zq4, Kc[r], Kc[4096 + q], Er, &Wr, &Wpq);
            float2 wq = cmul(Eq, Eq);                 // W^q
            float2 wr = make_float2(-wq.x, wq.y);     // Er^2 = -conj(Eq^2)
            b0[SKM(2 * q, 1)]     = cadd(Wq, Wpq);
            b0[SKM(2 * q + 1, 1)] = cmulc(csub(Wq, Wpq), wq);
            b0[SKM(2 * r, 1)]     = cadd(Wr, Wnq);
            b0[SKM(2 * r + 1, 1)] = cmulc(csub(Wr, Wnq), wr);
        }
    }
    __syncthreads();

    stage_r8<1,1,2,2>(b0, b1, tws, tid);   __syncthreads();
    stage_r8<1,2,1,16>(b1, b0, tws, tid);  __syncthreads();
    stage_r8<1,1,1,128>(b0, b1, tws, tid); __syncthreads();

    {   // final inverse stage s=1024 (twiddle-free): store first half to global
        float2 v[8];
#pragma unroll
        for (int j = 0; j < 8; j++) v[j] = b1[SKM(tid + (j << 10), 1)];
        dft8<1>(v);
        float2* outr = (float2*)(out + (size_t)row * L_SEQ);
#pragma unroll
        for (int j = 0; j < 4; j++) outr[tid + (j << 10)] = v[j];
    }
}

// ---------------------------------------------------------------------------
extern "C" void kernel_launch(void* const* d_in, const int* in_sizes, int n_in,
                              void* d_out, int out_size) {
    const float* x;
    const float* kern;
    if (in_sizes[0] == NROWS * L_SEQ) {
        x    = (const float*)d_in[0];
        kern = (const float*)d_in[1];
    } else {
        x    = (const float*)d_in[1];
        kern = (const float*)d_in[0];
    }
    float* out = (float*)d_out;

    cudaFuncSetAttribute(kspec_kernel, cudaFuncAttributeMaxDynamicSharedMemorySize, SMEM_BYTES);
    cudaFuncSetAttribute(conv_kernel,  cudaFuncAttributeMaxDynamicSharedMemorySize, SMEM_BYTES);

    init_tw_kernel<<<8, NT>>>();
    kspec_kernel<<<NCHAN, NT, SMEM_BYTES>>>(kern);
    conv_kernel<<<NROWS, NT, SMEM_BYTES>>>(x, out);
}

// round 13
// speedup vs baseline: 1.0561x; 1.0561x over previous
#include <cuda_runtime.h>
#include <math.h>

// out[b,c,:] = irfft( rfft(x,16384) * Kspec[c], 16384 )[:8192]
// kspec: R11 radix-8 NT=1024 (unchanged). conv: NT=512 radix-16,
// fwd [16,16,16,(2)], inv [(2),16,16,16]; r2 seams + spectral multiply fused
// in registers; gmem I/O fused into first/last stages. 12 SMEM half-passes.

#define N_FFT   8192
#define HALF_N  4096
#define NTK     1024
#define NTC     512
#define L_SEQ   8192
#define NCHAN   256
#define NROWS   2048

#define SKM(a,M) ((a) + (M) * ((a) >> 4))
#define KBUF    9216
#define CB0     9728          // conv b0: written with M=3 in inv s=2
#define CB1     8704          // conv b1: M=1 only
#define TWT8    1024
#define TWT16   512
#define TWH_N   2052

__device__ float2 g_kspec[(size_t)NCHAN * (N_FFT + 1)];

__device__ __forceinline__ float2 cmul(float2 a, float2 b) {
    return make_float2(a.x * b.x - a.y * b.y, a.x * b.y + a.y * b.x);
}
__device__ __forceinline__ float2 cmulc(float2 a, float2 b) {   // a * conj(b)
    return make_float2(a.x * b.x + a.y * b.y, a.y * b.x - a.x * b.y);
}
__device__ __forceinline__ float2 cadd(float2 a, float2 b) { return make_float2(a.x + b.x, a.y + b.y); }
__device__ __forceinline__ float2 csub(float2 a, float2 b) { return make_float2(a.x - b.x, a.y - b.y); }

template <int INV>
__device__ __forceinline__ void dft8(float2* v) {
    const float u = 0.70710678118654752f;
    float2 apc = cadd(v[0], v[4]), amc = csub(v[0], v[4]);
    float2 bpd = cadd(v[2], v[6]), bmd = csub(v[2], v[6]);
    float2 E0 = cadd(apc, bpd), E2 = csub(apc, bpd), E1, E3;
    if (!INV) { E1 = make_float2(amc.x + bmd.y, amc.y - bmd.x); E3 = make_float2(amc.x - bmd.y, amc.y + bmd.x); }
    else      { E1 = make_float2(amc.x - bmd.y, amc.y + bmd.x); E3 = make_float2(amc.x + bmd.y, amc.y - bmd.x); }
    apc = cadd(v[1], v[5]); amc = csub(v[1], v[5]);
    bpd = cadd(v[3], v[7]); bmd = csub(v[3], v[7]);
    float2 O0 = cadd(apc, bpd), O2 = csub(apc, bpd), O1, O3;
    if (!INV) { O1 = make_float2(amc.x + bmd.y, amc.y - bmd.x); O3 = make_float2(amc.x - bmd.y, amc.y + bmd.x); }
    else      { O1 = make_float2(amc.x - bmd.y, amc.y + bmd.x); O3 = make_float2(amc.x + bmd.y, amc.y - bmd.x); }
    float2 T1, T2, T3;
    if (!INV) {
        T1 = make_float2(u * (O1.x + O1.y), u * (O1.y - O1.x));
        T2 = make_float2(O2.y, -O2.x);
        T3 = make_float2(u * (O3.y - O3.x), -u * (O3.x + O3.y));
    } else {
        T1 = make_float2(u * (O1.x - O1.y), u * (O1.x + O1.y));
        T2 = make_float2(-O2.y, O2.x);
        T3 = make_float2(-u * (O3.x + O3.y), u * (O3.x - O3.y));
    }
    v[0] = cadd(E0, O0); v[4] = csub(E0, O0);
    v[1] = cadd(E1, T1); v[5] = csub(E1, T1);
    v[2] = cadd(E2, T2); v[6] = csub(E2, T2);
    v[3] = cadd(E3, T3); v[7] = csub(E3, T3);
}

// forward dft8 with v[4..7] == 0 implied
__device__ __forceinline__ void dft8_half(float2* v) {
    const float u = 0.70710678118654752f;
    float2 E0 = cadd(v[0], v[2]), E2 = csub(v[0], v[2]);
    float2 E1 = make_float2(v[0].x + v[2].y, v[0].y - v[2].x);
    float2 E3 = make_float2(v[0].x - v[2].y, v[0].y + v[2].x);
    float2 O0 = cadd(v[1], v[3]), O2 = csub(v[1], v[3]);
    float2 O1 = make_float2(v[1].x + v[3].y, v[1].y - v[3].x);
    float2 O3 = make_float2(v[1].x - v[3].y, v[1].y + v[3].x);
    float2 T1 = make_float2(u * (O1.x + O1.y), u * (O1.y - O1.x));
    float2 T2 = make_float2(O2.y, -O2.x);
    float2 T3 = make_float2(u * (O3.y - O3.x), -u * (O3.x + O3.y));
    v[0] = cadd(E0, O0); v[4] = csub(E0, O0);
    v[1] = cadd(E1, T1); v[5] = csub(E1, T1);
    v[2] = cadd(E2, T2); v[6] = csub(E2, T2);
    v[3] = cadd(E3, T3); v[7] = csub(E3, T3);
}

// combine e8/o8 (DFT8 of even/odd samples) into 16-pt DFT in v
template <int INV>
__device__ __forceinline__ void dft16_combine(float2* v, const float2* e8, const float2* o8) {
    const float c1 = 0.92387953251128674f, s1 = 0.38268343236508977f;
    const float uu = 0.70710678118654752f;
    const float sg = INV ? 1.0f : -1.0f;
    float2 t;
    v[0] = cadd(e8[0], o8[0]);                       v[8]  = csub(e8[0], o8[0]);
    t = cmul(o8[1], make_float2(c1, sg * s1));  v[1] = cadd(e8[1], t); v[9]  = csub(e8[1], t);
    t = cmul(o8[2], make_float2(uu, sg * uu));  v[2] = cadd(e8[2], t); v[10] = csub(e8[2], t);
    t = cmul(o8[3], make_float2(s1, sg * c1));  v[3] = cadd(e8[3], t); v[11] = csub(e8[3], t);
    t = make_float2(-sg * o8[4].y, sg * o8[4].x);
    v[4] = cadd(e8[4], t); v[12] = csub(e8[4], t);
    t = cmul(o8[5], make_float2(-s1, sg * c1)); v[5] = cadd(e8[5], t); v[13] = csub(e8[5], t);
    t = cmul(o8[6], make_float2(-uu, sg * uu)); v[6] = cadd(e8[6], t); v[14] = csub(e8[6], t);
    t = cmul(o8[7], make_float2(-c1, sg * s1)); v[7] = cadd(e8[7], t); v[15] = csub(e8[7], t);
}

template <int INV>
__device__ __forceinline__ void dft16(float2* v) {
    float2 e8[8], o8[8];
#pragma unroll
    for (int j = 0; j < 8; j++) { e8[j] = v[2 * j]; o8[j] = v[2 * j + 1]; }
    dft8<INV>(e8); dft8<INV>(o8);
    dft16_combine<INV>(v, e8, o8);
}

// 16-pt DFT with inputs v[8..15] == 0 implied (zero-padded upper half)
__device__ __forceinline__ void dft16_half(float2* v) {
    float2 e8[8], o8[8];
    e8[0] = v[0]; e8[1] = v[2]; e8[2] = v[4]; e8[3] = v[6];
    o8[0] = v[1]; o8[1] = v[3]; o8[2] = v[5]; o8[3] = v[7];
    dft8_half(e8); dft8_half(o8);
    dft16_combine<0>(v, e8, o8);
}

// ---------- radix-8 stage (kspec, NT=1024) ----------
template <int INV, int RM, int WM>
__device__ __forceinline__ void stage_r8(const float2* __restrict__ x, float2* __restrict__ y,
                                         const float2* __restrict__ tws, int s, int tid) {
    const int q = tid & (s - 1);
    const int e = tid - q;
    float2 v[8];
#pragma unroll
    for (int j = 0; j < 8; j++) v[j] = x[SKM(tid + (j << 10), RM)];
    dft8<INV>(v);
    const int o = q + (e << 3);
    y[SKM(o, WM)] = v[0];
#pragma unroll
    for (int m = 1; m < 8; m++) {
        float2 w = tws[((m - 1) << 10) + e];
        y[SKM(o + m * s, WM)] = INV ? cmulc(v[m], w) : cmul(w, v[m]);
    }
}

// ---------- radix-16 stage (conv, NT=512) ----------
template <int INV, int RM, int WM, int S>
__device__ __forceinline__ void stage_r16(const float2* __restrict__ x, float2* __restrict__ y,
                                          const float2* __restrict__ tws, int tid) {
    const int q = tid & (S - 1);
    const int e = tid - q;
    float2 v[16];
#pragma unroll
    for (int j = 0; j < 16; j++) v[j] = x[SKM(tid + (j << 9), RM)];
    dft16<INV>(v);
    const int o = q + (e << 4);
    y[SKM(o, WM)] = v[0];
#pragma unroll
    for (int m = 1; m < 16; m++) {
        float2 w = tws[((m - 1) << 9) + e];
        y[SKM(o + m * S, WM)] = INV ? cmulc(v[m], w) : cmul(w, v[m]);
    }
}

// unpack pair: Z[k], Z[8192-k], E=e^{-i pi k/8192} -> X[k], X[8192-k]
__device__ __forceinline__ void unpack_pair(float2 Zk, float2 Zn, float2 E,
                                            float2* Xk, float2* Xn) {
    float2 A = make_float2(0.5f * (Zk.x + Zn.x), 0.5f * (Zk.y - Zn.y));
    float2 D = make_float2(0.5f * (Zk.x - Zn.x), 0.5f * (Zk.y + Zn.y));
    float2 B = make_float2(D.y, -D.x);
    float2 EB = cmul(E, B);
    *Xk = make_float2(A.x + EB.x, A.y + EB.y);
    *Xn = make_float2(A.x - EB.x, -(A.y - EB.y));
}

__device__ __forceinline__ void spec_pair(float2 Zk, float2 Zn, float2 Kk, float2 Kn,
                                          float2 E, float2* Wk, float2* Wn) {
    float2 Xk, Xn;
    unpack_pair(Zk, Zn, E, &Xk, &Xn);
    float2 Yk = cmul(Xk, Kk);
    float2 Yn = cmul(Xn, Kn);
    float2 Ay = make_float2(0.5f * (Yk.x + Yn.x), 0.5f * (Yk.y - Yn.y));
    float2 Dy = make_float2(0.5f * (Yk.x - Yn.x), 0.5f * (Yk.y + Yn.y));
    float2 By = cmulc(Dy, E);
    *Wk = make_float2(Ay.x - By.y,  Ay.y + By.x);
    *Wn = make_float2(Ay.x + By.y, -Ay.y + By.x);
}

__device__ __forceinline__ float smooth_squash(const float* rk, int i) {
    float ssum = 0.f;
#pragma unroll
    for (int d = -3; d <= 3; d++) {
        int j = i + d;
        j = (j < 0) ? -j : j;
        j = (j > L_SEQ - 1) ? (2 * (L_SEQ - 1) - j) : j;
        ssum += rk[j];
    }
    float v = ssum * (1.0f / 7.0f);
    float a = fabsf(v) - 0.003f;
    return (a > 0.f) ? copysignf(a, v) : 0.f;
}

// kspec smem: b0[KBUF] | b1[KBUF] | tws[7*1024] | twh[2052]
#define SMEM_K ((2 * KBUF + 7 * TWT8 + TWH_N) * (int)sizeof(float2))
// conv smem:  b0[CB0] | b1[CB1] | tws[15*512] | twh[2052]
#define SMEM_C ((CB0 + CB1 + 15 * TWT16 + TWH_N) * (int)sizeof(float2))

// ---------------------------------------------------------------------------
// kspec (R11 version, NT=1024, radix-8)
// ---------------------------------------------------------------------------
__global__ void __launch_bounds__(NTK, 1) kspec_kernel(const float* __restrict__ kern) {
    extern __shared__ float2 sm2[];
    float2* b0  = sm2;
    float2* b1  = sm2 + KBUF;
    float2* tws = sm2 + 2 * KBUF;
    float2* twh = tws + 7 * TWT8;
    float*  rk  = (float*)b1;

    const int c   = blockIdx.x;
    const int tid = threadIdx.x;
    const float* kr = kern + (size_t)c * L_SEQ;

    for (int i = tid; i < L_SEQ; i += NTK) rk[i] = kr[i];
    {
        float s, cc;
#pragma unroll
        for (int m = 1; m <= 7; m++) {
            sincospif((float)(m * tid) * (1.0f / 4096.0f), &s, &cc);
            tws[((m - 1) << 10) + tid] = make_float2(cc, -s);
        }
#pragma unroll
        for (int k = tid; k < TWH_N; k += NTK) {
            sincospif((float)k * (1.0f / 8192.0f), &s, &cc);
            twh[k] = make_float2(cc, -s);
        }
    }
    __syncthreads();

    {   // fused stage 1 (s=1) from smooth/squash registers -> b0 (M=1)
        float2 v[8];
#pragma unroll
        for (int j = 0; j < 4; j++) {
            const int n = tid + (j << 10);
            v[j] = make_float2(smooth_squash(rk, 2 * n), smooth_squash(rk, 2 * n + 1));
        }
        __syncthreads();           // rk (b1) fully read before b1 reused next stage
        dft8_half(v);
        const int o = tid << 3;
        b0[SKM(o, 1)] = v[0];
#pragma unroll
        for (int m = 1; m < 8; m++)
            b0[SKM(o + m, 1)] = cmul(tws[((m - 1) << 10) + tid], v[m]);
    }
    __syncthreads();
    stage_r8<0,1,2>(b0, b1, tws, 8, tid);   __syncthreads();
    stage_r8<0,2,1>(b1, b0, tws, 64, tid);  __syncthreads();
    stage_r8<0,1,1>(b0, b1, tws, 512, tid); __syncthreads();
    // P = b1 (M=1); fused r2 finisher + unpack + store (scaled 1/N)
    float2* Kc = g_kspec + (size_t)c * (N_FFT + 1);
    const float inv = 1.0f / (float)N_FFT;
#pragma unroll 1
    for (int u = 0; u < 2; u++) {
        const int q = tid + (u << 10);
        if (q == 0) {
            float2 Pa = b1[SKM(0,1)],    Pb = b1[SKM(4096,1)];
            float2 Pc = b1[SKM(2048,1)], Pd = b1[SKM(6144,1)];
            float2 Z0 = cadd(Pa, Pb), Z4 = csub(Pa, Pb);
            float2 Z2 = cadd(Pc, Pd), Z6 = csub(Pc, Pd);
            Kc[0]     = make_float2((Z0.x + Z0.y) * inv, 0.f);
            Kc[N_FFT] = make_float2((Z0.x - Z0.y) * inv, 0.f);
            Kc[4096]  = make_float2(Z4.x * inv, -Z4.y * inv);
            float2 X2, X6;
            unpack_pair(Z2, Z6, twh[2048], &X2, &X6);
            Kc[2048] = make_float2(X2.x * inv, X2.y * inv);
            Kc[6144] = make_float2(X6.x * inv, X6.y * inv);
        } else {
            const int r = 4096 - q;
            float2 Pa = b1[SKM(q,1)], Pb = b1[SKM(q + 4096,1)];
            float2 Pc = b1[SKM(r,1)], Pd = b1[SKM(r + 4096,1)];
            float2 Zq = cadd(Pa, Pb), Zq4 = csub(Pa, Pb);
            float2 Zr = cadd(Pc, Pd), Znq = csub(Pc, Pd);
            float2 Eq = twh[q];
            float2 Er = make_float2(-Eq.y, -Eq.x);        // E(4096-q)
            float2 Xq, Xnq, Xr, Xpq;
            unpack_pair(Zq, Znq, Eq, &Xq, &Xnq);
            unpack_pair(Zr, Zq4, Er, &Xr, &Xpq);
            Kc[q]         = make_float2(Xq.x * inv,  Xq.y * inv);
            Kc[N_FFT - q] = make_float2(Xnq.x * inv, Xnq.y * inv);
            Kc[r]         = make_float2(Xr.x * inv,  Xr.y * inv);
            Kc[4096 + q]  = make_float2(Xpq.x * inv, Xpq.y * inv);
        }
    }
}

// ---------------------------------------------------------------------------
// conv: NT=512, radix-16
// ---------------------------------------------------------------------------
__global__ void __launch_bounds__(NTC, 1) conv_kernel(const float* __restrict__ x,
                                                      float* __restrict__ out) {
    extern __shared__ float2 sm2[];
    float2* b0  = sm2;
    float2* b1  = sm2 + CB0;
    float2* tws = b1 + CB1;
    float2* twh = tws + 15 * TWT16;

    const int row = blockIdx.x;
    const int c   = row & (NCHAN - 1);
    const int tid = threadIdx.x;
    const float2* xr = (const float2*)(x + (size_t)row * L_SEQ);

    // stage-1 global loads FIRST (latency overlaps the sincospif table fill)
    float2 v1[8];
#pragma unroll
    for (int j = 0; j < 8; j++) v1[j] = xr[tid + (j << 9)];

    {   // fill twiddle tables: tws[(m-1)*512+e] = W_8192^{m e}; twh[k]=e^{-i pi k/8192}
        float s, cc;
#pragma unroll
        for (int m = 1; m <= 15; m++) {
            sincospif((float)(m * tid) * (1.0f / 4096.0f), &s, &cc);
            tws[((m - 1) << 9) + tid] = make_float2(cc, -s);
        }
#pragma unroll
        for (int k = tid; k < TWH_N; k += NTC) {
            sincospif((float)k * (1.0f / 8192.0f), &s, &cc);
            twh[k] = make_float2(cc, -s);
        }
    }
    __syncthreads();

    {   // fwd stage 1 (s=1, radix-16, upper half zero) -> b0 (M=1)
        float2 v[16];
#pragma unroll
        for (int j = 0; j < 8; j++) v[j] = v1[j];
        dft16_half(v);
        const int o = tid << 4;
        b0[SKM(o, 1)] = v[0];
#pragma unroll
        for (int m = 1; m < 16; m++)
            b0[SKM(o + m, 1)] = cmul(tws[((m - 1) << 9) + tid], v[m]);
    }
    __syncthreads();
    stage_r16<0,1,1,16>(b0, b1, tws, tid);  __syncthreads();
    stage_r16<0,1,1,256>(b1, b0, tws, tid); __syncthreads();
    // P = b0 (M=1)

    // fused: fwd r2 finisher + spectral multiply + inv r2 opener -> b1 (M=1)
    const float2* Kc = g_kspec + (size_t)c * (N_FFT + 1);
#pragma unroll 1
    for (int u = 0; u < 4; u++) {
        const int q = tid + (u << 9);
        if (q == 0) {
            float2 Pa = b0[SKM(0,1)],    Pb = b0[SKM(4096,1)];
            float2 Pc = b0[SKM(2048,1)], Pd = b0[SKM(6144,1)];
            float2 Z0 = cadd(Pa, Pb), Z4 = csub(Pa, Pb);
            float2 Z2 = cadd(Pc, Pd), Z6 = csub(Pc, Pd);
            float X0 = Z0.x + Z0.y, XN = Z0.x - Z0.y;
            float2 K0 = Kc[0], KN = Kc[N_FFT];
            float2 Y0 = make_float2(X0 * K0.x, X0 * K0.y);
            float2 YN = make_float2(XN * KN.x, XN * KN.y);
            float2 Ay = make_float2(0.5f * (Y0.x + YN.x), 0.5f * (Y0.y - YN.y));
            float2 Dy = make_float2(0.5f * (Y0.x - YN.x), 0.5f * (Y0.y + YN.y));
            float2 W0 = make_float2(Ay.x - Dy.y, Ay.y + Dy.x);
            float2 W4, Wd;
            spec_pair(Z4, Z4, Kc[4096], Kc[4096], make_float2(0.f, -1.f), &W4, &Wd);
            float2 W2, W6;
            spec_pair(Z2, Z6, Kc[2048], Kc[6144], twh[2048], &W2, &W6);
            b1[SKM(0,1)] = cadd(W0, W4);
            b1[SKM(1,1)] = csub(W0, W4);
            b1[SKM(4096,1)] = cadd(W2, W6);
            float2 t = csub(W2, W6);                 // * winv(2048) = i
            b1[SKM(4097,1)] = make_float2(-t.y, t.x);
        } else {
            const int r = 4096 - q;
            float2 Pa = b0[SKM(q,1)], Pb = b0[SKM(q + 4096,1)];
            float2 Pc = b0[SKM(r,1)], Pd = b0[SKM(r + 4096,1)];
            float2 Zq = cadd(Pa, Pb), Zq4 = csub(Pa, Pb);
            float2 Zr = cadd(Pc, Pd), Znq = csub(Pc, Pd);
            float2 Eq = twh[q];
            float2 Er = make_float2(-Eq.y, -Eq.x);
            float2 Wq, Wnq, Wr, Wpq;
            spec_pair(Zq, Znq, Kc[q], Kc[N_FFT - q], Eq, &Wq, &Wnq);
            spec_pair(Zr, Zq4, Kc[r], Kc[4096 + q], Er, &Wr, &Wpq);
            float2 wq = cmul(Eq, Eq);                 // W^q
            float2 wr = make_float2(-wq.x, wq.y);     // Er^2 = -conj(Eq^2)
            b1[SKM(2 * q, 1)]     = cadd(Wq, Wpq);
            b1[SKM(2 * q + 1, 1)] = cmulc(csub(Wq, Wpq), wq);
            b1[SKM(2 * r, 1)]     = cadd(Wr, Wnq);
            b1[SKM(2 * r + 1, 1)] = cmulc(csub(Wr, Wnq), wr);
        }
    }
    __syncthreads();

    stage_r16<1,1,3,2>(b1, b0, tws, tid);   __syncthreads();  // write M=3: conflict-free
    stage_r16<1,3,1,32>(b0, b1, tws, tid);  __syncthreads();

    {   // final inverse stage s=512 (e=0, twiddle-free): store first half to gmem
        float2 v[16];
#pragma unroll
        for (int j = 0; j < 16; j++) v[j] = b1[SKM(tid + (j << 9), 1)];
        dft16<1>(v);
        float2* outr = (float2*)(out + (size_t)row * L_SEQ);
#pragma unroll
        for (int m = 0; m < 8; m++) outr[tid + (m << 9)] = v[m];
    }
}

// ---------------------------------------------------------------------------
extern "C" void kernel_launch(void* const* d_in, const int* in_sizes, int n_in,
                              void* d_out, int out_size) {
    const float* x;
    const float* kern;
    if (in_sizes[0] == NROWS * L_SEQ) {
        x    = (const float*)d_in[0];
        kern = (const float*)d_in[1];
    } else {
        x    = (const float*)d_in[1];
        kern = (const float*)d_in[0];
    }
    float* out = (float*)d_out;

    cudaFuncSetAttribute(kspec_kernel, cudaFuncAttributeMaxDynamicSharedMemorySize, SMEM_K);
    cudaFuncSetAttribute(conv_kernel,  cudaFuncAttributeMaxDynamicSharedMemorySize, SMEM_C);

    kspec_kernel<<<NCHAN, NTK, SMEM_K>>>(kern);
    conv_kernel<<<NROWS, NTC, SMEM_C>>>(x, out);
}